// round 10
// baseline (speedup 1.0000x reference)
#include <cuda_runtime.h>
#include <cstdint>

typedef unsigned long long ull;

#define NMAX   100000
#define EMAX   2000000
#define F_IN   500
#define H1     64
#define C_OUT  40
#define KC     50        // k-chunk for GEMM1 (double-buffered)
#define KP2    (KC / 2)  // k-pairs per chunk = 25
#define KXP    52        // padded x-row stride in smem (floats)
#define KXP2   26        // in float2 units
#define BM     128       // rows per block in GEMM1
#define NCHUNK (F_IN / KC)
#define GT     512       // GEMM1 threads (16 warps x 8 rows = 128 rows)
#define NBMAX  128

// Scratch (allocation-free rule: __device__ globals)
__device__ int   g_degi[NMAX];
__device__ float g_dinv[NMAX];
__device__ float g_h1  [(size_t)NMAX * H1];
__device__ float g_t2  [(size_t)NMAX * C_OUT];
__device__ int   g_src [EMAX];
__device__ int   g_dst [EMAX];
__device__ int   g_adj [EMAX];
__device__ int   g_row [NMAX + 1];
__device__ int   g_cur [NMAX];
__device__ int   g_bsum[NBMAX];
__device__ int   g_boff[NBMAX];
__device__ int   g_is64;

// ---------- packed-f32 helpers ----------
__device__ __forceinline__ ull pack2(float lo, float hi) {
    ull r;
    asm("mov.b64 %0, {%1, %2};" : "=l"(r) : "f"(lo), "f"(hi));
    return r;
}
__device__ __forceinline__ void ffma2(ull& d, ull a, ull b) {
    asm("fma.rn.f32x2 %0, %1, %2, %0;" : "+l"(d) : "l"(a), "l"(b));
}

// ---------- edge dtype detection ----------
__global__ void k_detect(const void* __restrict__ ei, int E, int n) {
    const long long* p = (const long long*)ei;
    int m = min(4096, E);
    int bad = 0;
    for (int i = threadIdx.x; i < m; i += blockDim.x) {
        long long v = p[i];
        if (v < 0 || v >= (long long)n) bad = 1;
    }
    bad = __syncthreads_or(bad);
    if (threadIdx.x == 0) g_is64 = bad ? 0 : 1;
}

__global__ void k_zero(int n) {
    int i = blockIdx.x * blockDim.x + threadIdx.x;
    if (i < n) g_degi[i] = 0;
}

// ---------- fused: edge int32 conversion + degree histogram ----------
__global__ void k_convert_hist(const void* __restrict__ ei, int E) {
    int i = blockIdx.x * blockDim.x + threadIdx.x;
    if (i >= E) return;
    int s, d;
    if (g_is64) {
        const long long* p = (const long long*)ei;
        s = (int)p[i];
        d = (int)p[E + i];
    } else {
        const int* p = (const int*)ei;
        s = p[i];
        d = p[E + i];
    }
    g_src[i] = s;
    g_dst[i] = d;
    atomicAdd(&g_degi[d], 1);
}

// ---------- GEMM1 (launch #4 -> profiled): h1 = dinv * (x @ W1) ----------
// 512 threads = 16 warps x 8 rows; warp covers all 64 cols (lane -> {lane, lane+32}).
// W pre-packed f32x2 in smem (conflict-free LDS.64); x broadcast LDS.64.
// Double-buffered x and W chunks. 79KB smem -> 2 CTAs/SM -> 8 warps/SMSP.
__global__ void __launch_bounds__(GT)
k_gemm1(const float* __restrict__ x, const float* __restrict__ W, int n) {
    extern __shared__ float sm[];
    float* xs0 = sm;                               // [BM][KXP]
    float* xs1 = xs0 + BM * KXP;                   // [BM][KXP]
    ull*   wp0 = (ull*)(xs1 + BM * KXP);           // [KP2][H1] packed k-pairs
    ull*   wp1 = wp0 + KP2 * H1;                   // [KP2][H1]

    const int tid  = threadIdx.x;
    const int lane = tid & 31;
    const int wrow = (tid >> 5) << 3;              // warp's first local row (0..120)
    const int row0 = blockIdx.x * BM;

    ull acc[8][2];
    #pragma unroll
    for (int r = 0; r < 8; r++) { acc[r][0] = 0ull; acc[r][1] = 0ull; }

    const float2* __restrict__ x2 = (const float2*)x;

    // ---- stage chunk 0 ----
    #pragma unroll 1
    for (int i = tid; i < BM * KP2; i += GT) {           // x as float2
        int r = i / KP2;
        int j = i - r * KP2;
        int row = row0 + r;
        ((float2*)xs0)[r * KXP2 + j] =
            (row < n) ? x2[(size_t)row * (F_IN / 2) + j] : make_float2(0.f, 0.f);
    }
    #pragma unroll 1
    for (int i = tid; i < KP2 * H1; i += GT) {           // packed W pairs
        int kp = i >> 6;
        int c  = i & 63;
        wp0[i] = pack2(W[(2 * kp) * H1 + c], W[(2 * kp + 1) * H1 + c]);
    }
    __syncthreads();

    for (int c = 0; c < NCHUNK; c++) {
        float* xcur = (c & 1) ? xs1 : xs0;
        float* xnxt = (c & 1) ? xs0 : xs1;
        ull*   wcur = (c & 1) ? wp1 : wp0;
        ull*   wnxt = (c & 1) ? wp0 : wp1;

        if (c + 1 < NCHUNK) {
            const int kc1  = (c + 1) * KC;
            const int kco2 = kc1 / 2;
            #pragma unroll 1
            for (int i = tid; i < BM * KP2; i += GT) {
                int r = i / KP2;
                int j = i - r * KP2;
                int row = row0 + r;
                ((float2*)xnxt)[r * KXP2 + j] =
                    (row < n) ? x2[(size_t)row * (F_IN / 2) + kco2 + j] : make_float2(0.f, 0.f);
            }
            #pragma unroll 1
            for (int i = tid; i < KP2 * H1; i += GT) {
                int kp = i >> 6;
                int cc = i & 63;
                wnxt[i] = pack2(W[(kc1 + 2 * kp) * H1 + cc], W[(kc1 + 2 * kp + 1) * H1 + cc]);
            }
        }

        #pragma unroll 5
        for (int kp = 0; kp < KP2; kp++) {
            const ull wA = wcur[kp * H1 + lane];           // contiguous 8B/lane
            const ull wB = wcur[kp * H1 + 32 + lane];
            #pragma unroll
            for (int r = 0; r < 8; r++) {
                const ull xv = *(const ull*)&xcur[(wrow + r) * KXP + 2 * kp];  // broadcast
                ffma2(acc[r][0], xv, wA);
                ffma2(acc[r][1], xv, wB);
            }
        }
        __syncthreads();
    }

    #pragma unroll
    for (int r = 0; r < 8; r++) {
        const int row = row0 + wrow + r;
        if (row < n) {
            const float dd = rsqrtf((float)g_degi[row] + 1.0f);  // +1 self-loop
            if (lane == 0) g_dinv[row] = dd;
            float2 v0 = *(float2*)&acc[r][0];
            float2 v1 = *(float2*)&acc[r][1];
            g_h1[(size_t)row * H1 + lane]      = dd * (v0.x + v0.y);
            g_h1[(size_t)row * H1 + 32 + lane] = dd * (v1.x + v1.y);
        }
    }
}

// ---------- CSR build: block scan over degrees ----------
__global__ void __launch_bounds__(1024)
k_scanA(int n) {
    __shared__ int s0[1024], s1[1024];
    const int tid = threadIdx.x;
    const int i = blockIdx.x * 1024 + tid;
    int v = (i < n) ? g_degi[i] : 0;
    s0[tid] = v;
    __syncthreads();
    int* a = s0; int* b = s1;
    #pragma unroll
    for (int off = 1; off < 1024; off <<= 1) {
        b[tid] = a[tid] + ((tid >= off) ? a[tid - off] : 0);
        __syncthreads();
        int* t = a; a = b; b = t;
    }
    if (i < n) g_row[i] = a[tid] - v;
    if (tid == 1023) g_bsum[blockIdx.x] = a[1023];
}
__global__ void __launch_bounds__(NBMAX)
k_scanB(int nb) {
    __shared__ int s0[NBMAX], s1[NBMAX];
    const int tid = threadIdx.x;
    int v = (tid < nb) ? g_bsum[tid] : 0;
    s0[tid] = v;
    __syncthreads();
    int* a = s0; int* b = s1;
    #pragma unroll
    for (int off = 1; off < NBMAX; off <<= 1) {
        b[tid] = a[tid] + ((tid >= off) ? a[tid - off] : 0);
        __syncthreads();
        int* t = a; a = b; b = t;
    }
    if (tid < nb) g_boff[tid] = a[tid] - v;
}
__global__ void k_scanC(int n, int E) {
    int i = blockIdx.x * blockDim.x + threadIdx.x;
    if (i < n) {
        int r = g_row[i] + g_boff[i >> 10];
        g_row[i] = r;
        g_cur[i] = r;
    }
    if (i == 0) g_row[n] = E;
}
__global__ void k_fill(int E) {
    int e = blockIdx.x * blockDim.x + threadIdx.x;
    if (e >= E) return;
    int pos = atomicAdd(&g_cur[g_dst[e]], 1);
    g_adj[pos] = g_src[e];
}

// ---------- fused layer-1 aggregate + bias + relu + GEMM2: warp per node ----------
__global__ void __launch_bounds__(256)
k_l1(const float* __restrict__ b1, const float* __restrict__ W2, int n) {
    __shared__ float W2s[H1 * C_OUT];
    __shared__ float b1s[H1];
    const int tid = threadIdx.x;
    for (int i = tid; i < H1 * C_OUT; i += 256) W2s[i] = W2[i];
    if (tid < H1) b1s[tid] = b1[tid];
    __syncthreads();

    const int lane = tid & 31;
    const int d = blockIdx.x * 8 + (tid >> 5);
    if (d >= n) return;

    const int beg = g_row[d];
    const int end = g_row[d + 1];
    const float2* __restrict__ h2 = (const float2*)g_h1;

    float2 a0 = h2[(size_t)d * 32 + lane];   // self-loop
    float2 a1 = make_float2(0.f, 0.f);
    float2 a2 = make_float2(0.f, 0.f);
    float2 a3 = make_float2(0.f, 0.f);

    int i = beg;
    for (; i + 8 <= end; i += 8) {
        int s[8];
        #pragma unroll
        for (int j = 0; j < 8; j++) s[j] = g_adj[i + j];
        float2 v[8];
        #pragma unroll
        for (int j = 0; j < 8; j++) v[j] = h2[(size_t)s[j] * 32 + lane];
        a0.x += v[0].x; a0.y += v[0].y;  a1.x += v[1].x; a1.y += v[1].y;
        a2.x += v[2].x; a2.y += v[2].y;  a3.x += v[3].x; a3.y += v[3].y;
        a0.x += v[4].x; a0.y += v[4].y;  a1.x += v[5].x; a1.y += v[5].y;
        a2.x += v[6].x; a2.y += v[6].y;  a3.x += v[7].x; a3.y += v[7].y;
    }
    for (; i < end; i++) {
        float2 v = h2[(size_t)g_adj[i] * 32 + lane];
        a0.x += v.x; a0.y += v.y;
    }
    a0.x += a1.x + a2.x + a3.x;
    a0.y += a1.y + a2.y + a3.y;

    const float dd = g_dinv[d];
    const float hx = fmaxf(a0.x * dd + b1s[2 * lane],     0.0f);
    const float hy = fmaxf(a0.y * dd + b1s[2 * lane + 1], 0.0f);

    float c0 = 0.0f, c1 = 0.0f;
    #pragma unroll
    for (int k2 = 0; k2 < 32; k2++) {
        const float ha = __shfl_sync(0xffffffffu, hx, k2);
        const float hb = __shfl_sync(0xffffffffu, hy, k2);
        c0 += ha * W2s[(2 * k2)     * C_OUT + lane];
        c0 += hb * W2s[(2 * k2 + 1) * C_OUT + lane];
        if (lane < 8) {
            c1 += ha * W2s[(2 * k2)     * C_OUT + 32 + lane];
            c1 += hb * W2s[(2 * k2 + 1) * C_OUT + 32 + lane];
        }
    }
    g_t2[(size_t)d * C_OUT + lane] = c0 * dd;
    if (lane < 8) g_t2[(size_t)d * C_OUT + 32 + lane] = c1 * dd;
}

// ---------- fused layer-2 aggregate + bias + relu + log_softmax: warp per node ----------
__global__ void __launch_bounds__(256)
k_l2(float* __restrict__ out, const float* __restrict__ b2, int n) {
    __shared__ float b2s[C_OUT];
    const int tid = threadIdx.x;
    if (tid < C_OUT) b2s[tid] = b2[tid];
    __syncthreads();

    const int lane = tid & 31;
    const int d = blockIdx.x * 8 + (tid >> 5);
    if (d >= n) return;

    const int beg = g_row[d];
    const int end = g_row[d + 1];
    const bool lo8 = (lane < 8);

    float aa0 = g_t2[(size_t)d * C_OUT + lane];
    float ab0 = lo8 ? g_t2[(size_t)d * C_OUT + 32 + lane] : 0.0f;
    float aa1 = 0.f, ab1 = 0.f, aa2 = 0.f, ab2 = 0.f, aa3 = 0.f, ab3 = 0.f;

    int i = beg;
    for (; i + 8 <= end; i += 8) {
        int s[8];
        #pragma unroll
        for (int j = 0; j < 8; j++) s[j] = g_adj[i + j];
        float va[8];
        #pragma unroll
        for (int j = 0; j < 8; j++) va[j] = g_t2[(size_t)s[j] * C_OUT + lane];
        aa0 += va[0]; aa1 += va[1]; aa2 += va[2]; aa3 += va[3];
        aa0 += va[4]; aa1 += va[5]; aa2 += va[6]; aa3 += va[7];
        if (lo8) {
            float vb[8];
            #pragma unroll
            for (int j = 0; j < 8; j++) vb[j] = g_t2[(size_t)s[j] * C_OUT + 32 + lane];
            ab0 += vb[0]; ab1 += vb[1]; ab2 += vb[2]; ab3 += vb[3];
            ab0 += vb[4]; ab1 += vb[5]; ab2 += vb[6]; ab3 += vb[7];
        }
    }
    for (; i < end; i++) {
        int s = g_adj[i];
        aa0 += g_t2[(size_t)s * C_OUT + lane];
        if (lo8) ab0 += g_t2[(size_t)s * C_OUT + 32 + lane];
    }
    aa0 += aa1 + aa2 + aa3;
    ab0 += ab1 + ab2 + ab3;

    const float dd = g_dinv[d];
    const float v0 = fmaxf(aa0 * dd + b2s[lane], 0.0f);
    const float v1 = lo8 ? fmaxf(ab0 * dd + b2s[32 + lane], 0.0f) : -1e30f;

    float m = fmaxf(v0, v1);
    #pragma unroll
    for (int o = 16; o; o >>= 1) m = fmaxf(m, __shfl_xor_sync(0xffffffffu, m, o));
    float s = expf(v0 - m) + (lo8 ? expf(v1 - m) : 0.0f);
    #pragma unroll
    for (int o = 16; o; o >>= 1) s += __shfl_xor_sync(0xffffffffu, s, o);
    const float lse = m + logf(s);

    out[(size_t)d * C_OUT + lane] = v0 - lse;
    if (lo8) out[(size_t)d * C_OUT + 32 + lane] = v1 - lse;
}

extern "C" void kernel_launch(void* const* d_in, const int* in_sizes, int n_in,
                              void* d_out, int out_size) {
    const float* x  = (const float*)d_in[0];
    const void*  ei = d_in[1];
    const float* W1 = (const float*)d_in[2];
    const float* b1 = (const float*)d_in[3];
    const float* W2 = (const float*)d_in[4];
    const float* b2 = (const float*)d_in[5];
    float*       out = (float*)d_out;

    const int n = in_sizes[0] / F_IN;
    const int E = in_sizes[1] / 2;
    const int nb = (n + 1023) / 1024;

    k_detect      <<<1, 256>>>(ei, E, n);                 // launch 1
    k_zero        <<<(n + 255) / 256, 256>>>(n);          // launch 2
    k_convert_hist<<<(E + 255) / 256, 256>>>(ei, E);      // launch 3

    const int smem = (2 * BM * KXP) * (int)sizeof(float)
                   + 2 * KP2 * H1 * (int)sizeof(ull);     // ~79KB
    cudaFuncSetAttribute(k_gemm1, cudaFuncAttributeMaxDynamicSharedMemorySize, smem);
    k_gemm1<<<(n + BM - 1) / BM, GT, smem>>>(x, W1, n);   // launch 4 (profiled)

    k_scanA <<<nb, 1024>>>(n);
    k_scanB <<<1, NBMAX>>>(nb);
    k_scanC <<<(n + 255) / 256, 256>>>(n, E);
    k_fill  <<<(E + 255) / 256, 256>>>(E);

    k_l1<<<(n + 7) / 8, 256>>>(b1, W2, n);
    k_l2<<<(n + 7) / 8, 256>>>(out, b2, n);
}

// round 11
// speedup vs baseline: 1.2520x; 1.2520x over previous
#include <cuda_runtime.h>
#include <cstdint>

typedef unsigned long long ull;

#define NMAX   100000
#define EMAX   2000000
#define F_IN   500
#define H1     64
#define C_OUT  40
#define BM     128            // rows per CTA tile
#define KC     64             // k per chunk
#define NCHUNK 8              // 8*64 = 512 >= 500 (zero-padded)
#define GT     256            // 8 warps
#define XSTR   68             // x smem row stride (floats): bank = 4*tr+tc, conflict-free
#define WSTR   72             // W smem row stride (floats): bank = 8*tc+tr, conflict-free
#define XBUF   (BM * XSTR)    // 8704 floats
#define WBUF   (KC * WSTR)    // 4608 floats
#define NBMAX  128

// Scratch (allocation-free rule: __device__ globals)
__device__ int   g_degi[NMAX];
__device__ float g_dinv[NMAX];
__device__ float g_h1  [(size_t)NMAX * H1];
__device__ float g_t2  [(size_t)NMAX * C_OUT];
__device__ int   g_src [EMAX];
__device__ int   g_dst [EMAX];
__device__ int   g_adj [EMAX];
__device__ int   g_row [NMAX + 1];
__device__ int   g_cur [NMAX];
__device__ int   g_bsum[NBMAX];
__device__ int   g_boff[NBMAX];
__device__ int   g_is64;

// ---------- helpers ----------
__device__ __forceinline__ float to_tf32(float f) {
    float r;
    asm("cvt.rna.tf32.f32 %0, %1;" : "=f"(r) : "f"(f));
    return r;
}
__device__ __forceinline__ void mma_tf32(
    float& d0, float& d1, float& d2, float& d3,
    uint32_t a0, uint32_t a1, uint32_t a2, uint32_t a3,
    uint32_t b0, uint32_t b1) {
    asm volatile(
        "mma.sync.aligned.m16n8k8.row.col.f32.tf32.tf32.f32 "
        "{%0,%1,%2,%3}, {%4,%5,%6,%7}, {%8,%9}, {%0,%1,%2,%3};"
        : "+f"(d0), "+f"(d1), "+f"(d2), "+f"(d3)
        : "r"(a0), "r"(a1), "r"(a2), "r"(a3), "r"(b0), "r"(b1));
}

// ---------- edge dtype detection ----------
__global__ void k_detect(const void* __restrict__ ei, int E, int n) {
    const long long* p = (const long long*)ei;
    int m = min(4096, E);
    int bad = 0;
    for (int i = threadIdx.x; i < m; i += blockDim.x) {
        long long v = p[i];
        if (v < 0 || v >= (long long)n) bad = 1;
    }
    bad = __syncthreads_or(bad);
    if (threadIdx.x == 0) g_is64 = bad ? 0 : 1;
}

__global__ void k_zero(int n) {
    int i = blockIdx.x * blockDim.x + threadIdx.x;
    if (i < n) g_degi[i] = 0;
}

// ---------- fused: edge int32 conversion + degree histogram ----------
__global__ void k_convert_hist(const void* __restrict__ ei, int E) {
    int i = blockIdx.x * blockDim.x + threadIdx.x;
    if (i >= E) return;
    int s, d;
    if (g_is64) {
        const long long* p = (const long long*)ei;
        s = (int)p[i];
        d = (int)p[E + i];
    } else {
        const int* p = (const int*)ei;
        s = p[i];
        d = p[E + i];
    }
    g_src[i] = s;
    g_dst[i] = d;
    atomicAdd(&g_degi[d], 1);
}

// ---------- GEMM1 (launch #4 -> profiled): h1 = dinv * (x @ W1), tensor cores ----------
// mma.sync.m16n8k8.tf32. Warp = 16 rows x 64 cols (8 MMAs per k8 step).
// x & W tf32-staged in smem, double-buffered; conflict-free fragment LDS.
__global__ void __launch_bounds__(GT)
k_gemm1(const float* __restrict__ x, const float* __restrict__ W, int n) {
    extern __shared__ float sm[];
    float* xs[2] = { sm, sm + XBUF };
    float* ws[2] = { sm + 2 * XBUF, sm + 2 * XBUF + WBUF };

    const int tid  = threadIdx.x;
    const int lane = tid & 31;
    const int wid  = tid >> 5;           // 0..7
    const int tr   = lane >> 2;          // 0..7
    const int tc   = lane & 3;           // 0..3
    const int row0 = blockIdx.x * BM;
    const int wr   = wid * 16;           // warp's first local row

    float d[8][4];
    #pragma unroll
    for (int j = 0; j < 8; j++)
        #pragma unroll
        for (int q = 0; q < 4; q++) d[j][q] = 0.0f;

    const float4* __restrict__ x4 = (const float4*)x;   // 125 float4 per row
    const float4* __restrict__ W4 = (const float4*)W;   // 16 float4 per k-row

    // ---- staging lambda-ish macro via plain code: stage chunk c into buffer b ----
    // x: 128 rows x 16 float4 ; W: 64 krows x 16 float4
    #define STAGE(cc, bb)                                                          \
    {                                                                              \
        const int kc4 = (cc) * (KC / 4);                                           \
        _Pragma("unroll 1")                                                        \
        for (int i = tid; i < BM * (KC / 4); i += GT) {                            \
            int r = i >> 4, q = i & 15;                                            \
            int row = row0 + r;                                                    \
            float4 v = make_float4(0.f, 0.f, 0.f, 0.f);                            \
            if (row < n && (kc4 + q) < (F_IN / 4))                                 \
                v = x4[(size_t)row * (F_IN / 4) + kc4 + q];                        \
            v.x = to_tf32(v.x); v.y = to_tf32(v.y);                                \
            v.z = to_tf32(v.z); v.w = to_tf32(v.w);                                \
            *(float4*)&xs[bb][r * XSTR + 4 * q] = v;                               \
        }                                                                          \
        _Pragma("unroll 1")                                                        \
        for (int i = tid; i < KC * (H1 / 4); i += GT) {                            \
            int kl = i >> 4, q = i & 15;                                           \
            int k = (cc) * KC + kl;                                                \
            float4 v = make_float4(0.f, 0.f, 0.f, 0.f);                            \
            if (k < F_IN)                                                          \
                v = W4[(size_t)k * (H1 / 4) + q];                                  \
            v.x = to_tf32(v.x); v.y = to_tf32(v.y);                                \
            v.z = to_tf32(v.z); v.w = to_tf32(v.w);                                \
            *(float4*)&ws[bb][kl * WSTR + 4 * q] = v;                              \
        }                                                                          \
    }

    STAGE(0, 0)
    __syncthreads();

    for (int c = 0; c < NCHUNK; c++) {
        const int cur = c & 1;
        if (c + 1 < NCHUNK) STAGE(c + 1, cur ^ 1)

        const float* xb = xs[cur];
        const float* wb = ws[cur];
        const uint32_t* xa_lo = (const uint32_t*)(xb + (wr + tr) * XSTR + tc);
        const uint32_t* xa_hi = (const uint32_t*)(xb + (wr + tr + 8) * XSTR + tc);
        const uint32_t* wb0 = (const uint32_t*)(wb + tc * WSTR + tr);
        const uint32_t* wb1 = (const uint32_t*)(wb + (tc + 4) * WSTR + tr);

        #pragma unroll
        for (int s = 0; s < KC / 8; s++) {
            const int kk = 8 * s;
            const uint32_t a0 = xa_lo[kk];
            const uint32_t a1 = xa_hi[kk];
            const uint32_t a2 = xa_lo[kk + 4];
            const uint32_t a3 = xa_hi[kk + 4];
            #pragma unroll
            for (int j = 0; j < 8; j++) {
                const uint32_t b0 = wb0[kk * WSTR + 8 * j];
                const uint32_t b1 = wb1[kk * WSTR + 8 * j];
                mma_tf32(d[j][0], d[j][1], d[j][2], d[j][3], a0, a1, a2, a3, b0, b1);
            }
        }
        __syncthreads();
    }
    #undef STAGE

    // ---- epilogue: dinv scale + store ----
    const int r_lo = row0 + wr + tr;
    const int r_hi = r_lo + 8;
    if (r_lo < n) {
        const float dd = rsqrtf((float)g_degi[r_lo] + 1.0f);
        if (tc == 0) g_dinv[r_lo] = dd;
        #pragma unroll
        for (int j = 0; j < 8; j++) {
            float2 v = make_float2(dd * d[j][0], dd * d[j][1]);
            *(float2*)&g_h1[(size_t)r_lo * H1 + 8 * j + 2 * tc] = v;
        }
    }
    if (r_hi < n) {
        const float dd = rsqrtf((float)g_degi[r_hi] + 1.0f);
        if (tc == 0) g_dinv[r_hi] = dd;
        #pragma unroll
        for (int j = 0; j < 8; j++) {
            float2 v = make_float2(dd * d[j][2], dd * d[j][3]);
            *(float2*)&g_h1[(size_t)r_hi * H1 + 8 * j + 2 * tc] = v;
        }
    }
}

// ---------- CSR build: block scan over degrees ----------
__global__ void __launch_bounds__(1024)
k_scanA(int n) {
    __shared__ int s0[1024], s1[1024];
    const int tid = threadIdx.x;
    const int i = blockIdx.x * 1024 + tid;
    int v = (i < n) ? g_degi[i] : 0;
    s0[tid] = v;
    __syncthreads();
    int* a = s0; int* b = s1;
    #pragma unroll
    for (int off = 1; off < 1024; off <<= 1) {
        b[tid] = a[tid] + ((tid >= off) ? a[tid - off] : 0);
        __syncthreads();
        int* t = a; a = b; b = t;
    }
    if (i < n) g_row[i] = a[tid] - v;
    if (tid == 1023) g_bsum[blockIdx.x] = a[1023];
}
__global__ void __launch_bounds__(NBMAX)
k_scanB(int nb) {
    __shared__ int s0[NBMAX], s1[NBMAX];
    const int tid = threadIdx.x;
    int v = (tid < nb) ? g_bsum[tid] : 0;
    s0[tid] = v;
    __syncthreads();
    int* a = s0; int* b = s1;
    #pragma unroll
    for (int off = 1; off < NBMAX; off <<= 1) {
        b[tid] = a[tid] + ((tid >= off) ? a[tid - off] : 0);
        __syncthreads();
        int* t = a; a = b; b = t;
    }
    if (tid < nb) g_boff[tid] = a[tid] - v;
}
__global__ void k_scanC(int n, int E) {
    int i = blockIdx.x * blockDim.x + threadIdx.x;
    if (i < n) {
        int r = g_row[i] + g_boff[i >> 10];
        g_row[i] = r;
        g_cur[i] = r;
    }
    if (i == 0) g_row[n] = E;
}
__global__ void k_fill(int E) {
    int e = blockIdx.x * blockDim.x + threadIdx.x;
    if (e >= E) return;
    int pos = atomicAdd(&g_cur[g_dst[e]], 1);
    g_adj[pos] = g_src[e];
}

// ---------- fused layer-1 aggregate + bias + relu + GEMM2: warp per node ----------
__global__ void __launch_bounds__(256)
k_l1(const float* __restrict__ b1, const float* __restrict__ W2, int n) {
    __shared__ float W2s[H1 * C_OUT];
    __shared__ float b1s[H1];
    const int tid = threadIdx.x;
    for (int i = tid; i < H1 * C_OUT; i += 256) W2s[i] = W2[i];
    if (tid < H1) b1s[tid] = b1[tid];
    __syncthreads();

    const int lane = tid & 31;
    const int d = blockIdx.x * 8 + (tid >> 5);
    if (d >= n) return;

    const int beg = g_row[d];
    const int end = g_row[d + 1];
    const float2* __restrict__ h2 = (const float2*)g_h1;

    float2 a0 = h2[(size_t)d * 32 + lane];   // self-loop
    float2 a1 = make_float2(0.f, 0.f);
    float2 a2 = make_float2(0.f, 0.f);
    float2 a3 = make_float2(0.f, 0.f);

    int i = beg;
    for (; i + 8 <= end; i += 8) {
        int s[8];
        #pragma unroll
        for (int j = 0; j < 8; j++) s[j] = g_adj[i + j];
        float2 v[8];
        #pragma unroll
        for (int j = 0; j < 8; j++) v[j] = h2[(size_t)s[j] * 32 + lane];
        a0.x += v[0].x; a0.y += v[0].y;  a1.x += v[1].x; a1.y += v[1].y;
        a2.x += v[2].x; a2.y += v[2].y;  a3.x += v[3].x; a3.y += v[3].y;
        a0.x += v[4].x; a0.y += v[4].y;  a1.x += v[5].x; a1.y += v[5].y;
        a2.x += v[6].x; a2.y += v[6].y;  a3.x += v[7].x; a3.y += v[7].y;
    }
    for (; i < end; i++) {
        float2 v = h2[(size_t)g_adj[i] * 32 + lane];
        a0.x += v.x; a0.y += v.y;
    }
    a0.x += a1.x + a2.x + a3.x;
    a0.y += a1.y + a2.y + a3.y;

    const float dd = g_dinv[d];
    const float hx = fmaxf(a0.x * dd + b1s[2 * lane],     0.0f);
    const float hy = fmaxf(a0.y * dd + b1s[2 * lane + 1], 0.0f);

    float c0 = 0.0f, c1 = 0.0f;
    #pragma unroll
    for (int k2 = 0; k2 < 32; k2++) {
        const float ha = __shfl_sync(0xffffffffu, hx, k2);
        const float hb = __shfl_sync(0xffffffffu, hy, k2);
        c0 += ha * W2s[(2 * k2)     * C_OUT + lane];
        c0 += hb * W2s[(2 * k2 + 1) * C_OUT + lane];
        if (lane < 8) {
            c1 += ha * W2s[(2 * k2)     * C_OUT + 32 + lane];
            c1 += hb * W2s[(2 * k2 + 1) * C_OUT + 32 + lane];
        }
    }
    g_t2[(size_t)d * C_OUT + lane] = c0 * dd;
    if (lane < 8) g_t2[(size_t)d * C_OUT + 32 + lane] = c1 * dd;
}

// ---------- fused layer-2 aggregate + bias + relu + log_softmax: warp per node ----------
__global__ void __launch_bounds__(256)
k_l2(float* __restrict__ out, const float* __restrict__ b2, int n) {
    __shared__ float b2s[C_OUT];
    const int tid = threadIdx.x;
    if (tid < C_OUT) b2s[tid] = b2[tid];
    __syncthreads();

    const int lane = tid & 31;
    const int d = blockIdx.x * 8 + (tid >> 5);
    if (d >= n) return;

    const int beg = g_row[d];
    const int end = g_row[d + 1];
    const bool lo8 = (lane < 8);

    float aa0 = g_t2[(size_t)d * C_OUT + lane];
    float ab0 = lo8 ? g_t2[(size_t)d * C_OUT + 32 + lane] : 0.0f;
    float aa1 = 0.f, ab1 = 0.f, aa2 = 0.f, ab2 = 0.f, aa3 = 0.f, ab3 = 0.f;

    int i = beg;
    for (; i + 8 <= end; i += 8) {
        int s[8];
        #pragma unroll
        for (int j = 0; j < 8; j++) s[j] = g_adj[i + j];
        float va[8];
        #pragma unroll
        for (int j = 0; j < 8; j++) va[j] = g_t2[(size_t)s[j] * C_OUT + lane];
        aa0 += va[0]; aa1 += va[1]; aa2 += va[2]; aa3 += va[3];
        aa0 += va[4]; aa1 += va[5]; aa2 += va[6]; aa3 += va[7];
        if (lo8) {
            float vb[8];
            #pragma unroll
            for (int j = 0; j < 8; j++) vb[j] = g_t2[(size_t)s[j] * C_OUT + 32 + lane];
            ab0 += vb[0]; ab1 += vb[1]; ab2 += vb[2]; ab3 += vb[3];
            ab0 += vb[4]; ab1 += vb[5]; ab2 += vb[6]; ab3 += vb[7];
        }
    }
    for (; i < end; i++) {
        int s = g_adj[i];
        aa0 += g_t2[(size_t)s * C_OUT + lane];
        if (lo8) ab0 += g_t2[(size_t)s * C_OUT + 32 + lane];
    }
    aa0 += aa1 + aa2 + aa3;
    ab0 += ab1 + ab2 + ab3;

    const float dd = g_dinv[d];
    const float v0 = fmaxf(aa0 * dd + b2s[lane], 0.0f);
    const float v1 = lo8 ? fmaxf(ab0 * dd + b2s[32 + lane], 0.0f) : -1e30f;

    float m = fmaxf(v0, v1);
    #pragma unroll
    for (int o = 16; o; o >>= 1) m = fmaxf(m, __shfl_xor_sync(0xffffffffu, m, o));
    float s = expf(v0 - m) + (lo8 ? expf(v1 - m) : 0.0f);
    #pragma unroll
    for (int o = 16; o; o >>= 1) s += __shfl_xor_sync(0xffffffffu, s, o);
    const float lse = m + logf(s);

    out[(size_t)d * C_OUT + lane] = v0 - lse;
    if (lo8) out[(size_t)d * C_OUT + 32 + lane] = v1 - lse;
}

extern "C" void kernel_launch(void* const* d_in, const int* in_sizes, int n_in,
                              void* d_out, int out_size) {
    const float* x  = (const float*)d_in[0];
    const void*  ei = d_in[1];
    const float* W1 = (const float*)d_in[2];
    const float* b1 = (const float*)d_in[3];
    const float* W2 = (const float*)d_in[4];
    const float* b2 = (const float*)d_in[5];
    float*       out = (float*)d_out;

    const int n = in_sizes[0] / F_IN;
    const int E = in_sizes[1] / 2;
    const int nb = (n + 1023) / 1024;

    k_detect      <<<1, 256>>>(ei, E, n);                 // launch 1
    k_zero        <<<(n + 255) / 256, 256>>>(n);          // launch 2
    k_convert_hist<<<(E + 255) / 256, 256>>>(ei, E);      // launch 3

    const int smem = (2 * XBUF + 2 * WBUF) * (int)sizeof(float);  // ~104KB
    cudaFuncSetAttribute(k_gemm1, cudaFuncAttributeMaxDynamicSharedMemorySize, smem);
    k_gemm1<<<(n + BM - 1) / BM, GT, smem>>>(x, W1, n);   // launch 4 (profiled)

    k_scanA <<<nb, 1024>>>(n);
    k_scanB <<<1, NBMAX>>>(nb);
    k_scanC <<<(n + 255) / 256, 256>>>(n, E);
    k_fill  <<<(E + 255) / 256, 256>>>(E);

    k_l1<<<(n + 7) / 8, 256>>>(b1, W2, n);
    k_l2<<<(n + 7) / 8, 256>>>(out, b2, n);
}

// round 12
// speedup vs baseline: 1.6423x; 1.3118x over previous
#include <cuda_runtime.h>
#include <cstdint>

typedef unsigned long long ull;

#define NMAX   100000
#define EMAX   2000000
#define F_IN   500
#define H1     64
#define C_OUT  40
#define BM     256            // rows per CTA tile (16 warps x 16 rows)
#define GW     16             // warps
#define GT     512            // threads
#define KC     32             // k per chunk
#define NCHUNK 16             // 16*32 = 512 >= 500 (zero-padded)
#define WROWS  512
#define XSTR   36             // x smem row stride (floats): bank 4*tr+tc, conflict-free
#define WSTR   72             // W smem row stride (floats): bank 8*tc+tr, conflict-free
#define NBMAX  128

// Scratch (allocation-free rule: __device__ globals)
__device__ int   g_degi[NMAX];
__device__ float g_dinv[NMAX];
__device__ float g_h1  [(size_t)NMAX * H1];
__device__ float g_t2  [(size_t)NMAX * C_OUT];
__device__ int   g_src [EMAX];
__device__ int   g_dst [EMAX];
__device__ int   g_adj [EMAX];
__device__ int   g_row [NMAX + 1];
__device__ int   g_cur [NMAX];
__device__ int   g_bsum[NBMAX];
__device__ int   g_boff[NBMAX];
__device__ int   g_is64;

// ---------- helpers ----------
__device__ __forceinline__ float to_tf32(float f) {
    float r;
    asm("cvt.rna.tf32.f32 %0, %1;" : "=f"(r) : "f"(f));
    return r;
}
__device__ __forceinline__ void mma_tf32(
    float& d0, float& d1, float& d2, float& d3,
    uint32_t a0, uint32_t a1, uint32_t a2, uint32_t a3,
    uint32_t b0, uint32_t b1) {
    asm volatile(
        "mma.sync.aligned.m16n8k8.row.col.f32.tf32.tf32.f32 "
        "{%0,%1,%2,%3}, {%4,%5,%6,%7}, {%8,%9}, {%0,%1,%2,%3};"
        : "+f"(d0), "+f"(d1), "+f"(d2), "+f"(d3)
        : "r"(a0), "r"(a1), "r"(a2), "r"(a3), "r"(b0), "r"(b1));
}
__device__ __forceinline__ uint32_t smem_u32(const void* p) {
    return (uint32_t)__cvta_generic_to_shared(p);
}
__device__ __forceinline__ void cp16(uint32_t dst, const void* src, int srcsize) {
    asm volatile("cp.async.cg.shared.global [%0], [%1], 16, %2;"
                 :: "r"(dst), "l"(src), "r"(srcsize) : "memory");
}

// ---------- edge dtype detection ----------
__global__ void k_detect(const void* __restrict__ ei, int E, int n) {
    const long long* p = (const long long*)ei;
    int m = min(4096, E);
    int bad = 0;
    for (int i = threadIdx.x; i < m; i += blockDim.x) {
        long long v = p[i];
        if (v < 0 || v >= (long long)n) bad = 1;
    }
    bad = __syncthreads_or(bad);
    if (threadIdx.x == 0) g_is64 = bad ? 0 : 1;
}

__global__ void k_zero(int n) {
    int i = blockIdx.x * blockDim.x + threadIdx.x;
    if (i < n) g_degi[i] = 0;
}

// ---------- fused: edge int32 conversion + degree histogram ----------
__global__ void k_convert_hist(const void* __restrict__ ei, int E) {
    int i = blockIdx.x * blockDim.x + threadIdx.x;
    if (i >= E) return;
    int s, d;
    if (g_is64) {
        const long long* p = (const long long*)ei;
        s = (int)p[i];
        d = (int)p[E + i];
    } else {
        const int* p = (const int*)ei;
        s = p[i];
        d = p[E + i];
    }
    g_src[i] = s;
    g_dst[i] = d;
    atomicAdd(&g_degi[d], 1);
}

// ---------- GEMM1 (launch #4 -> profiled): h1 = dinv * (x @ W1) ----------
// mma.sync.m16n8k8.tf32. W resident in smem (staged once); x per-warp
// double-buffered via cp.async -> NO CTA barriers in the mainloop.
__global__ void __launch_bounds__(GT)
k_gemm1(const float* __restrict__ x, const float* __restrict__ W, int n) {
    extern __shared__ float sm[];
    float* ws = sm;                         // [512][WSTR]
    float* xs = sm + WROWS * WSTR;          // [GW][2][16][XSTR]

    const int tid  = threadIdx.x;
    const int lane = tid & 31;
    const int w    = tid >> 5;              // 0..15
    const int tr   = lane >> 2;             // 0..7
    const int tc   = lane & 3;              // 0..3
    const int row0 = blockIdx.x * BM;
    const int wr   = w * 16;                // warp's first local row

    float* xw = xs + w * (2 * 16 * XSTR);   // this warp's two buffers
    const uint32_t xw_u32 = smem_u32(xw);

    // per-lane cp.async geometry: 2 lanes per row, 4 x 16B each
    const int lrow  = lane >> 1;            // 0..15 local row
    const int lhalf = lane & 1;             // 0/1 -> float4 group
    const int grow  = row0 + wr + lrow;     // global row this lane stages
    const bool rok  = (grow < n);
    const float* gbase = x + (size_t)(rok ? grow : 0) * F_IN;

    // issue chunk cc into buffer bb (per-warp, no sync)
    #define ISSUE(cc, bb)                                                       \
    {                                                                           \
        _Pragma("unroll")                                                       \
        for (int q = 0; q < 4; q++) {                                           \
            const int f4 = lhalf * 4 + q;            /* float4 idx in row */    \
            const int kg = (cc) * KC + f4 * 4;                                  \
            const int ok = (rok && (kg + 4 <= F_IN)) ? 16 : 0;                  \
            const uint32_t dst = xw_u32 +                                       \
                (uint32_t)(((bb) * 16 + lrow) * XSTR + f4 * 4) * 4u;            \
            cp16(dst, gbase + kg, ok);                                          \
        }                                                                       \
        asm volatile("cp.async.commit_group;" ::: "memory");                    \
    }

    // prologue: start chunks 0,1 before W staging so LDG/cp.async overlap
    ISSUE(0, 0)
    ISSUE(1, 1)

    // stage all of W (zero-padded to 512 rows), tf32-rounded
    const float4* __restrict__ W4 = (const float4*)W;
    #pragma unroll 1
    for (int i = tid; i < WROWS * (H1 / 4); i += GT) {
        const int k = i >> 4, q = i & 15;
        float4 v = make_float4(0.f, 0.f, 0.f, 0.f);
        if (k < F_IN) v = W4[(size_t)k * (H1 / 4) + q];
        v.x = to_tf32(v.x); v.y = to_tf32(v.y);
        v.z = to_tf32(v.z); v.w = to_tf32(v.w);
        *(float4*)&ws[k * WSTR + 4 * q] = v;
    }
    __syncthreads();   // W visible to all; the ONLY CTA barrier

    float d[8][4];
    #pragma unroll
    for (int j = 0; j < 8; j++)
        #pragma unroll
        for (int q = 0; q < 4; q++) d[j][q] = 0.0f;

    for (int c = 0; c < NCHUNK; c++) {
        asm volatile("cp.async.wait_group 1;" ::: "memory");
        __syncwarp();

        const int buf = c & 1;
        const float* xb = xw + buf * (16 * XSTR);
        const uint32_t* xa_lo = (const uint32_t*)(xb + tr * XSTR + tc);
        const uint32_t* xa_hi = (const uint32_t*)(xb + (tr + 8) * XSTR + tc);
        const uint32_t* wb0 = (const uint32_t*)(ws + (c * KC + tc) * WSTR + tr);
        const uint32_t* wb1 = (const uint32_t*)(ws + (c * KC + tc + 4) * WSTR + tr);

        #pragma unroll
        for (int s = 0; s < KC / 8; s++) {
            const int kk = 8 * s;
            const uint32_t a0 = xa_lo[kk];
            const uint32_t a1 = xa_hi[kk];
            const uint32_t a2 = xa_lo[kk + 4];
            const uint32_t a3 = xa_hi[kk + 4];
            #pragma unroll
            for (int j = 0; j < 8; j++) {
                const uint32_t b0 = wb0[kk * WSTR + 8 * j];
                const uint32_t b1 = wb1[kk * WSTR + 8 * j];
                mma_tf32(d[j][0], d[j][1], d[j][2], d[j][3], a0, a1, a2, a3, b0, b1);
            }
        }

        if (c + 2 < NCHUNK) {
            ISSUE(c + 2, buf)
        } else {
            asm volatile("cp.async.commit_group;" ::: "memory");  // empty group
        }
    }
    #undef ISSUE

    // ---- epilogue: dinv scale + store (mapping verified in R11) ----
    const int r_lo = row0 + wr + tr;
    const int r_hi = r_lo + 8;
    if (r_lo < n) {
        const float dd = rsqrtf((float)g_degi[r_lo] + 1.0f);
        if (tc == 0) g_dinv[r_lo] = dd;
        #pragma unroll
        for (int j = 0; j < 8; j++) {
            float2 v = make_float2(dd * d[j][0], dd * d[j][1]);
            *(float2*)&g_h1[(size_t)r_lo * H1 + 8 * j + 2 * tc] = v;
        }
    }
    if (r_hi < n) {
        const float dd = rsqrtf((float)g_degi[r_hi] + 1.0f);
        if (tc == 0) g_dinv[r_hi] = dd;
        #pragma unroll
        for (int j = 0; j < 8; j++) {
            float2 v = make_float2(dd * d[j][2], dd * d[j][3]);
            *(float2*)&g_h1[(size_t)r_hi * H1 + 8 * j + 2 * tc] = v;
        }
    }
}

// ---------- CSR build: block scan over degrees ----------
__global__ void __launch_bounds__(1024)
k_scanA(int n) {
    __shared__ int s0[1024], s1[1024];
    const int tid = threadIdx.x;
    const int i = blockIdx.x * 1024 + tid;
    int v = (i < n) ? g_degi[i] : 0;
    s0[tid] = v;
    __syncthreads();
    int* a = s0; int* b = s1;
    #pragma unroll
    for (int off = 1; off < 1024; off <<= 1) {
        b[tid] = a[tid] + ((tid >= off) ? a[tid - off] : 0);
        __syncthreads();
        int* t = a; a = b; b = t;
    }
    if (i < n) g_row[i] = a[tid] - v;
    if (tid == 1023) g_bsum[blockIdx.x] = a[1023];
}
__global__ void __launch_bounds__(NBMAX)
k_scanB(int nb) {
    __shared__ int s0[NBMAX], s1[NBMAX];
    const int tid = threadIdx.x;
    int v = (tid < nb) ? g_bsum[tid] : 0;
    s0[tid] = v;
    __syncthreads();
    int* a = s0; int* b = s1;
    #pragma unroll
    for (int off = 1; off < NBMAX; off <<= 1) {
        b[tid] = a[tid] + ((tid >= off) ? a[tid - off] : 0);
        __syncthreads();
        int* t = a; a = b; b = t;
    }
    if (tid < nb) g_boff[tid] = a[tid] - v;
}
__global__ void k_scanC(int n, int E) {
    int i = blockIdx.x * blockDim.x + threadIdx.x;
    if (i < n) {
        int r = g_row[i] + g_boff[i >> 10];
        g_row[i] = r;
        g_cur[i] = r;
    }
    if (i == 0) g_row[n] = E;
}
__global__ void k_fill(int E) {
    int e = blockIdx.x * blockDim.x + threadIdx.x;
    if (e >= E) return;
    int pos = atomicAdd(&g_cur[g_dst[e]], 1);
    g_adj[pos] = g_src[e];
}

// ---------- fused layer-1 aggregate + bias + relu + GEMM2: warp per node ----------
__global__ void __launch_bounds__(256)
k_l1(const float* __restrict__ b1, const float* __restrict__ W2, int n) {
    __shared__ float W2s[H1 * C_OUT];
    __shared__ float b1s[H1];
    const int tid = threadIdx.x;
    for (int i = tid; i < H1 * C_OUT; i += 256) W2s[i] = W2[i];
    if (tid < H1) b1s[tid] = b1[tid];
    __syncthreads();

    const int lane = tid & 31;
    const int d = blockIdx.x * 8 + (tid >> 5);
    if (d >= n) return;

    const int beg = g_row[d];
    const int end = g_row[d + 1];
    const float2* __restrict__ h2 = (const float2*)g_h1;

    float2 a0 = h2[(size_t)d * 32 + lane];   // self-loop
    float2 a1 = make_float2(0.f, 0.f);
    float2 a2 = make_float2(0.f, 0.f);
    float2 a3 = make_float2(0.f, 0.f);

    int i = beg;
    for (; i + 8 <= end; i += 8) {
        int s[8];
        #pragma unroll
        for (int j = 0; j < 8; j++) s[j] = g_adj[i + j];
        float2 v[8];
        #pragma unroll
        for (int j = 0; j < 8; j++) v[j] = h2[(size_t)s[j] * 32 + lane];
        a0.x += v[0].x; a0.y += v[0].y;  a1.x += v[1].x; a1.y += v[1].y;
        a2.x += v[2].x; a2.y += v[2].y;  a3.x += v[3].x; a3.y += v[3].y;
        a0.x += v[4].x; a0.y += v[4].y;  a1.x += v[5].x; a1.y += v[5].y;
        a2.x += v[6].x; a2.y += v[6].y;  a3.x += v[7].x; a3.y += v[7].y;
    }
    for (; i < end; i++) {
        float2 v = h2[(size_t)g_adj[i] * 32 + lane];
        a0.x += v.x; a0.y += v.y;
    }
    a0.x += a1.x + a2.x + a3.x;
    a0.y += a1.y + a2.y + a3.y;

    const float dd = g_dinv[d];
    const float hx = fmaxf(a0.x * dd + b1s[2 * lane],     0.0f);
    const float hy = fmaxf(a0.y * dd + b1s[2 * lane + 1], 0.0f);

    float c0 = 0.0f, c1 = 0.0f;
    #pragma unroll
    for (int k2 = 0; k2 < 32; k2++) {
        const float ha = __shfl_sync(0xffffffffu, hx, k2);
        const float hb = __shfl_sync(0xffffffffu, hy, k2);
        c0 += ha * W2s[(2 * k2)     * C_OUT + lane];
        c0 += hb * W2s[(2 * k2 + 1) * C_OUT + lane];
        if (lane < 8) {
            c1 += ha * W2s[(2 * k2)     * C_OUT + 32 + lane];
            c1 += hb * W2s[(2 * k2 + 1) * C_OUT + 32 + lane];
        }
    }
    g_t2[(size_t)d * C_OUT + lane] = c0 * dd;
    if (lane < 8) g_t2[(size_t)d * C_OUT + 32 + lane] = c1 * dd;
}

// ---------- fused layer-2 aggregate + bias + relu + log_softmax: warp per node ----------
__global__ void __launch_bounds__(256)
k_l2(float* __restrict__ out, const float* __restrict__ b2, int n) {
    __shared__ float b2s[C_OUT];
    const int tid = threadIdx.x;
    if (tid < C_OUT) b2s[tid] = b2[tid];
    __syncthreads();

    const int lane = tid & 31;
    const int d = blockIdx.x * 8 + (tid >> 5);
    if (d >= n) return;

    const int beg = g_row[d];
    const int end = g_row[d + 1];
    const bool lo8 = (lane < 8);

    float aa0 = g_t2[(size_t)d * C_OUT + lane];
    float ab0 = lo8 ? g_t2[(size_t)d * C_OUT + 32 + lane] : 0.0f;
    float aa1 = 0.f, ab1 = 0.f, aa2 = 0.f, ab2 = 0.f, aa3 = 0.f, ab3 = 0.f;

    int i = beg;
    for (; i + 8 <= end; i += 8) {
        int s[8];
        #pragma unroll
        for (int j = 0; j < 8; j++) s[j] = g_adj[i + j];
        float va[8];
        #pragma unroll
        for (int j = 0; j < 8; j++) va[j] = g_t2[(size_t)s[j] * C_OUT + lane];
        aa0 += va[0]; aa1 += va[1]; aa2 += va[2]; aa3 += va[3];
        aa0 += va[4]; aa1 += va[5]; aa2 += va[6]; aa3 += va[7];
        if (lo8) {
            float vb[8];
            #pragma unroll
            for (int j = 0; j < 8; j++) vb[j] = g_t2[(size_t)s[j] * C_OUT + 32 + lane];
            ab0 += vb[0]; ab1 += vb[1]; ab2 += vb[2]; ab3 += vb[3];
            ab0 += vb[4]; ab1 += vb[5]; ab2 += vb[6]; ab3 += vb[7];
        }
    }
    for (; i < end; i++) {
        int s = g_adj[i];
        aa0 += g_t2[(size_t)s * C_OUT + lane];
        if (lo8) ab0 += g_t2[(size_t)s * C_OUT + 32 + lane];
    }
    aa0 += aa1 + aa2 + aa3;
    ab0 += ab1 + ab2 + ab3;

    const float dd = g_dinv[d];
    const float v0 = fmaxf(aa0 * dd + b2s[lane], 0.0f);
    const float v1 = lo8 ? fmaxf(ab0 * dd + b2s[32 + lane], 0.0f) : -1e30f;

    float m = fmaxf(v0, v1);
    #pragma unroll
    for (int o = 16; o; o >>= 1) m = fmaxf(m, __shfl_xor_sync(0xffffffffu, m, o));
    float s = expf(v0 - m) + (lo8 ? expf(v1 - m) : 0.0f);
    #pragma unroll
    for (int o = 16; o; o >>= 1) s += __shfl_xor_sync(0xffffffffu, s, o);
    const float lse = m + logf(s);

    out[(size_t)d * C_OUT + lane] = v0 - lse;
    if (lo8) out[(size_t)d * C_OUT + 32 + lane] = v1 - lse;
}

extern "C" void kernel_launch(void* const* d_in, const int* in_sizes, int n_in,
                              void* d_out, int out_size) {
    const float* x  = (const float*)d_in[0];
    const void*  ei = d_in[1];
    const float* W1 = (const float*)d_in[2];
    const float* b1 = (const float*)d_in[3];
    const float* W2 = (const float*)d_in[4];
    const float* b2 = (const float*)d_in[5];
    float*       out = (float*)d_out;

    const int n = in_sizes[0] / F_IN;
    const int E = in_sizes[1] / 2;
    const int nb = (n + 1023) / 1024;

    k_detect      <<<1, 256>>>(ei, E, n);                 // launch 1
    k_zero        <<<(n + 255) / 256, 256>>>(n);          // launch 2
    k_convert_hist<<<(E + 255) / 256, 256>>>(ei, E);      // launch 3

    const int smem = (WROWS * WSTR + GW * 2 * 16 * XSTR) * (int)sizeof(float); // 221184 B
    cudaFuncSetAttribute(k_gemm1, cudaFuncAttributeMaxDynamicSharedMemorySize, smem);
    k_gemm1<<<(n + BM - 1) / BM, GT, smem>>>(x, W1, n);   // launch 4 (profiled)

    k_scanA <<<nb, 1024>>>(n);
    k_scanB <<<1, NBMAX>>>(nb);
    k_scanC <<<(n + 255) / 256, 256>>>(n, E);
    k_fill  <<<(E + 255) / 256, 256>>>(E);

    k_l1<<<(n + 7) / 8, 256>>>(b1, W2, n);
    k_l2<<<(n + 7) / 8, 256>>>(out, b2, n);
}